// round 1
// baseline (speedup 1.0000x reference)
#include <cuda_runtime.h>
#include <cuda_bf16.h>
#include <math.h>

#define N_NODES 100000
#define N_EDGES 1600000
#define HID 128
#define ED 32
#define NGRAPH 64

// ---------------- device scratch (allocation-free rule: static globals) ----------------
__device__ float g_h[N_NODES * HID];        // node features
__device__ float g_PA[N_NODES * 256];       // per-node dst-parts: [f(128) | s(128)] (+biases)
__device__ float g_PB[N_NODES * 256];       // per-node src-parts: [f(128) | s(128)]
__device__ float g_agg[N_NODES * HID];      // aggregation buffer (also reused for conv1 agg [N*3])
__device__ float g_pool[NGRAPH * HID + NGRAPH]; // sums + counts

// ---------------- helpers ----------------
__device__ __forceinline__ float sigmoidf_(float x) {
    return 1.0f / (1.0f + __expf(-x));
}
__device__ __forceinline__ float softplusf_(float x) {
    // stable: max(x,0) + log(1 + exp(-|x|))
    return fmaxf(x, 0.0f) + __logf(1.0f + __expf(-fabsf(x)));
}
__device__ __forceinline__ void red4(float* p, float4 v) {
    asm volatile("red.global.add.v4.f32 [%0], {%1,%2,%3,%4};"
                 :: "l"(p), "f"(v.x), "f"(v.y), "f"(v.z), "f"(v.w) : "memory");
}

// ---------------- zero ----------------
__global__ void k_zero(float* __restrict__ p, int n) {
    int i = blockIdx.x * blockDim.x + threadIdx.x;
    int stride = gridDim.x * blockDim.x;
    for (; i < n; i += stride) p[i] = 0.0f;
}

// ---------------- conv1 (C=3): per-edge full evaluation ----------------
__global__ void k_conv1(const float* __restrict__ x, const int* __restrict__ ei,
                        const float* __restrict__ ea,
                        const float* __restrict__ Wf, const float* __restrict__ bf,
                        const float* __restrict__ Ws, const float* __restrict__ bs,
                        float* __restrict__ agg) {
    __shared__ float sWf[38 * 3], sWs[38 * 3], sbf[3], sbs[3];
    int t = threadIdx.x;
    if (t < 114) { sWf[t] = Wf[t]; sWs[t] = Ws[t]; }
    if (t < 3)   { sbf[t] = bf[t]; sbs[t] = bs[t]; }
    __syncthreads();
    int e = blockIdx.x * blockDim.x + t;
    if (e >= N_EDGES) return;
    int src = ei[e];
    int dst = ei[N_EDGES + e];
    float z[38];
    z[0] = x[dst * 3 + 0]; z[1] = x[dst * 3 + 1]; z[2] = x[dst * 3 + 2];
    z[3] = x[src * 3 + 0]; z[4] = x[src * 3 + 1]; z[5] = x[src * 3 + 2];
#pragma unroll
    for (int k = 0; k < 32; k++) z[6 + k] = ea[e * 32 + k];
#pragma unroll
    for (int c = 0; c < 3; c++) {
        float lf = sbf[c], ls = sbs[c];
#pragma unroll
        for (int k = 0; k < 38; k++) {
            lf += z[k] * sWf[k * 3 + c];
            ls += z[k] * sWs[k * 3 + c];
        }
        float m = sigmoidf_(lf) * softplusf_(ls);
        atomicAdd(&agg[dst * 3 + c], m);
    }
}

// ---------------- node projection after conv1: h = relu((x+agg) @ Wp + bp) ----------------
__global__ void k_node1(const float* __restrict__ x, const float* __restrict__ agg,
                        const float* __restrict__ Wp, const float* __restrict__ bp,
                        float* __restrict__ h) {
    int n = blockIdx.x;
    int c = threadIdx.x;  // 128 threads
    __shared__ float sx[3];
    if (c < 3) sx[c] = x[n * 3 + c] + agg[n * 3 + c];
    __syncthreads();
    float v = bp[c] + sx[0] * Wp[c] + sx[1] * Wp[128 + c] + sx[2] * Wp[256 + c];
    h[n * HID + c] = fmaxf(v, 0.0f);
}

// ---------------- per-node projections for a hidden conv ----------------
// part 0: PA[:,0:128]  = h @ Wf[0:128]   + bf
// part 1: PA[:,128:256]= h @ Ws[0:128]   + bs
// part 2: PB[:,0:128]  = h @ Wf[128:256]
// part 3: PB[:,128:256]= h @ Ws[128:256]
__global__ __launch_bounds__(256) void k_proj(
        const float* __restrict__ h,
        const float* __restrict__ Wf, const float* __restrict__ Ws,
        const float* __restrict__ bf, const float* __restrict__ bs,
        float* __restrict__ PA, float* __restrict__ PB) {
    int part = blockIdx.y;
    const float* W; const float* bias; float* out; int coloff;
    if (part == 0)      { W = Wf;              bias = bf;      out = PA; coloff = 0;   }
    else if (part == 1) { W = Ws;              bias = bs;      out = PA; coloff = 128; }
    else if (part == 2) { W = Wf + 128 * 128;  bias = nullptr; out = PB; coloff = 0;   }
    else                { W = Ws + 128 * 128;  bias = nullptr; out = PB; coloff = 128; }

    __shared__ float hs[64][36];        // 64 nodes x 32 k (padded)
    __shared__ float4 ws4[32][32];      // 32 k x 128 cols

    int t = threadIdx.x;                // 256 threads
    int lane = t & 31;
    int grp = t >> 5;                   // 0..7
    int n0 = blockIdx.x * 64;

    float4 binit = make_float4(0.f, 0.f, 0.f, 0.f);
    if (bias) binit = *(const float4*)&bias[lane * 4];

    float4 acc[8];
#pragma unroll
    for (int i = 0; i < 8; i++) acc[i] = binit;

    for (int kt = 0; kt < 4; kt++) {
        int k0 = kt * 32;
        // load h tile: 512 float4 total, 2 per thread
#pragma unroll
        for (int j = 0; j < 2; j++) {
            int idx = t * 2 + j;
            int n = idx >> 3;
            int kk = (idx & 7) * 4;
            float4 v = make_float4(0.f, 0.f, 0.f, 0.f);
            if (n0 + n < N_NODES) v = *(const float4*)&h[(n0 + n) * HID + k0 + kk];
            *(float4*)&hs[n][kk] = v;
        }
        // load W tile: 1024 float4, 4 per thread
#pragma unroll
        for (int j = 0; j < 4; j++) {
            int idx = t + j * 256;
            int kk = idx >> 5;
            int c4 = idx & 31;
            ws4[kk][c4] = *(const float4*)&W[(k0 + kk) * 128 + c4 * 4];
        }
        __syncthreads();
#pragma unroll
        for (int kk = 0; kk < 32; kk++) {
            float4 w = ws4[kk][lane];
#pragma unroll
            for (int i = 0; i < 8; i++) {
                float a = hs[grp * 8 + i][kk];
                acc[i].x += a * w.x;
                acc[i].y += a * w.y;
                acc[i].z += a * w.z;
                acc[i].w += a * w.w;
            }
        }
        __syncthreads();
    }
#pragma unroll
    for (int i = 0; i < 8; i++) {
        int n = n0 + grp * 8 + i;
        if (n < N_NODES)
            *(float4*)&out[n * 256 + coloff + lane * 4] = acc[i];
    }
}

// ---------------- edge kernel for hidden convs ----------------
// lf = PA_f[dst] + PB_f[src] + e@Wef ; ls = PA_s[dst] + PB_s[src] + e@Wes
// m = sigmoid(lf) * softplus(ls) ; agg[dst] += m
#define EPW 8
__global__ __launch_bounds__(256, 2) void k_edge(
        const int* __restrict__ ei, const float* __restrict__ ea,
        const float* __restrict__ PA, const float* __restrict__ PB,
        const float* __restrict__ Wef, const float* __restrict__ Wes,
        float* __restrict__ agg) {
    __shared__ float4 swf[32][32];     // 32 k x 128 cols (as float4)
    __shared__ float4 sws[32][32];
    __shared__ float sea[8][EPW][33];  // per-warp staged edge attrs

    int t = threadIdx.x;
    int lane = t & 31;
    int w = t >> 5;

    for (int i = t; i < 32 * 32; i += blockDim.x) {
        int kk = i >> 5, c4 = i & 31;
        swf[kk][c4] = *(const float4*)&Wef[kk * 128 + c4 * 4];
        sws[kk][c4] = *(const float4*)&Wes[kk * 128 + c4 * 4];
    }
    __syncthreads();

    const float4* PA4 = (const float4*)PA;
    const float4* PB4 = (const float4*)PB;

    int warpId = blockIdx.x * 8 + w;
    int nwarps = gridDim.x * 8;

    for (long e0 = (long)warpId * EPW; e0 < N_EDGES; e0 += (long)nwarps * EPW) {
        // N_EDGES % EPW == 0 -> always full batches
#pragma unroll
        for (int j = 0; j < EPW; j++)
            sea[w][j][lane] = ea[(e0 + j) * 32 + lane];
        __syncwarp();

        float4 accf[EPW], accs[EPW];
        int dsts[EPW];
#pragma unroll
        for (int j = 0; j < EPW; j++) {
            int e = (int)e0 + j;
            int src = ei[e];
            int dst = ei[N_EDGES + e];
            dsts[j] = dst;
            float4 af = PA4[(long)dst * 64 + lane];
            float4 as = PA4[(long)dst * 64 + 32 + lane];
            float4 bfv = PB4[(long)src * 64 + lane];
            float4 bsv = PB4[(long)src * 64 + 32 + lane];
            accf[j] = make_float4(af.x + bfv.x, af.y + bfv.y, af.z + bfv.z, af.w + bfv.w);
            accs[j] = make_float4(as.x + bsv.x, as.y + bsv.y, as.z + bsv.z, as.w + bsv.w);
        }
#pragma unroll
        for (int k = 0; k < 32; k++) {
            float4 wf = swf[k][lane];
            float4 wsv = sws[k][lane];
#pragma unroll
            for (int j = 0; j < EPW; j++) {
                float a = sea[w][j][k];
                accf[j].x += a * wf.x;  accf[j].y += a * wf.y;
                accf[j].z += a * wf.z;  accf[j].w += a * wf.w;
                accs[j].x += a * wsv.x; accs[j].y += a * wsv.y;
                accs[j].z += a * wsv.z; accs[j].w += a * wsv.w;
            }
        }
#pragma unroll
        for (int j = 0; j < EPW; j++) {
            float4 m;
            m.x = sigmoidf_(accf[j].x) * softplusf_(accs[j].x);
            m.y = sigmoidf_(accf[j].y) * softplusf_(accs[j].y);
            m.z = sigmoidf_(accf[j].z) * softplusf_(accs[j].z);
            m.w = sigmoidf_(accf[j].w) * softplusf_(accs[j].w);
            red4(&agg[(long)dsts[j] * HID + lane * 4], m);
        }
        __syncwarp();
    }
}

// ---------------- residual + relu ----------------
__global__ void k_update(float* __restrict__ h, const float* __restrict__ agg, int n) {
    int i = blockIdx.x * blockDim.x + threadIdx.x;
    int stride = gridDim.x * blockDim.x;
    for (; i < n; i += stride) h[i] = fmaxf(h[i] + agg[i], 0.0f);
}

// ---------------- pooling (batch is sorted) ----------------
__global__ void k_pool(const float* __restrict__ h, const int* __restrict__ batch,
                       float* __restrict__ pool, float* __restrict__ cnt) {
    const int NPB = 256;
    int n0 = blockIdx.x * NPB;
    if (n0 >= N_NODES) return;
    int c = threadIdx.x;  // 128 threads
    float s = 0.0f;
    int cur = batch[n0];
    int mycnt = 0;
    for (int i = 0; i < NPB; i++) {
        int n = n0 + i;
        if (n >= N_NODES) break;
        int b = batch[n];
        if (b != cur) {
            atomicAdd(&pool[cur * HID + c], s);
            if (c == 0) atomicAdd(&cnt[cur], (float)mycnt);
            s = 0.0f; mycnt = 0; cur = b;
        }
        s += h[n * HID + c];
        mycnt++;
    }
    atomicAdd(&pool[cur * HID + c], s);
    if (c == 0) atomicAdd(&cnt[cur], (float)mycnt);
}

// ---------------- head: relu(pooled @ W1 + b1) @ W2 + b2 ----------------
__global__ void k_head(const float* __restrict__ pool, const float* __restrict__ cnt,
                       const float* __restrict__ W1, const float* __restrict__ b1,
                       const float* __restrict__ W2, const float* __restrict__ b2,
                       float* __restrict__ out) {
    int g = blockIdx.x;
    int c = threadIdx.x;  // 128
    __shared__ float p[128];
    __shared__ float t1[128];
    float invc = 1.0f / fmaxf(cnt[g], 1.0f);
    p[c] = pool[g * HID + c] * invc;
    __syncthreads();
    float v = b1[c];
#pragma unroll 16
    for (int k = 0; k < 128; k++) v += p[k] * W1[k * 128 + c];
    t1[c] = fmaxf(v, 0.0f);
    __syncthreads();
    if (c < 3) {
        float o = b2[c];
        for (int k = 0; k < 128; k++) o += t1[k] * W2[k * 3 + c];
        out[g * 3 + c] = o;
    }
}

// ---------------- launch ----------------
extern "C" void kernel_launch(void* const* d_in, const int* in_sizes, int n_in,
                              void* d_out, int out_size) {
    const float* x   = (const float*)d_in[0];
    const int*   ei  = (const int*)d_in[1];
    const float* ea  = (const float*)d_in[2];
    const int*   bat = (const int*)d_in[3];
    const float* Wf1 = (const float*)d_in[4];
    const float* bf1 = (const float*)d_in[5];
    const float* Ws1 = (const float*)d_in[6];
    const float* bs1 = (const float*)d_in[7];
    const float* Wp  = (const float*)d_in[8];
    const float* bp  = (const float*)d_in[9];
    const float* Wc[2]  = { (const float*)d_in[10], (const float*)d_in[14] }; // Wf2, Wf3
    const float* bcf[2] = { (const float*)d_in[11], (const float*)d_in[15] };
    const float* Wsc[2] = { (const float*)d_in[12], (const float*)d_in[16] };
    const float* bcs[2] = { (const float*)d_in[13], (const float*)d_in[17] };
    const float* W1  = (const float*)d_in[18];
    const float* b1  = (const float*)d_in[19];
    const float* W2  = (const float*)d_in[20];
    const float* b2  = (const float*)d_in[21];
    float* out = (float*)d_out;

    float *pH, *pPA, *pPB, *pAgg, *pPool;
    cudaGetSymbolAddress((void**)&pH,    g_h);
    cudaGetSymbolAddress((void**)&pPA,   g_PA);
    cudaGetSymbolAddress((void**)&pPB,   g_PB);
    cudaGetSymbolAddress((void**)&pAgg,  g_agg);
    cudaGetSymbolAddress((void**)&pPool, g_pool);

    // conv1
    k_zero<<<512, 256>>>(pAgg, N_NODES * 3);
    k_conv1<<<(N_EDGES + 255) / 256, 256>>>(x, ei, ea, Wf1, bf1, Ws1, bs1, pAgg);
    k_node1<<<N_NODES, 128>>>(x, pAgg, Wp, bp, pH);

    // hidden convs
    for (int l = 0; l < 2; l++) {
        dim3 pg((N_NODES + 63) / 64, 4);
        k_proj<<<pg, 256>>>(pH, Wc[l], Wsc[l], bcf[l], bcs[l], pPA, pPB);
        k_zero<<<2048, 256>>>(pAgg, N_NODES * HID);
        k_edge<<<1184, 256>>>(ei, ea, pPA, pPB,
                              Wc[l] + 256 * 128, Wsc[l] + 256 * 128, pAgg);
        k_update<<<2048, 256>>>(pH, pAgg, N_NODES * HID);
    }

    // pooling + head
    k_zero<<<64, 256>>>(pPool, NGRAPH * HID + NGRAPH);
    k_pool<<<(N_NODES + 255) / 256, 128>>>(pH, bat, pPool, pPool + NGRAPH * HID);
    k_head<<<NGRAPH, 128>>>(pPool, pPool + NGRAPH * HID, W1, b1, W2, b2, out);
}

// round 2
// speedup vs baseline: 1.2061x; 1.2061x over previous
#include <cuda_runtime.h>
#include <cuda_fp16.h>
#include <math.h>

#define N_NODES 100000
#define N_EDGES 1600000
#define HID 128
#define NGRAPH 64
#define ETILE 64
#define NTILES (N_EDGES / ETILE)

// ---------------- device scratch ----------------
__device__ float  g_h[N_NODES * HID];
__device__ __half g_PA[N_NODES * 256];   // per-node dst-parts: [f(128)|s(128)] (+bias)
__device__ __half g_PB[N_NODES * 256];   // per-node src-parts
__device__ float  g_agg[N_NODES * HID];
__device__ float  g_pool[NGRAPH * HID + NGRAPH];

// ---------------- helpers ----------------
__device__ __forceinline__ float sigmoidf_(float x) { return 1.0f / (1.0f + __expf(-x)); }
__device__ __forceinline__ float softplusf_(float x) {
    return fmaxf(x, 0.0f) + __logf(1.0f + __expf(-fabsf(x)));
}
__device__ __forceinline__ void red4(float* p, float4 v) {
    asm volatile("red.global.add.v4.f32 [%0], {%1,%2,%3,%4};"
                 :: "l"(p), "f"(v.x), "f"(v.y), "f"(v.z), "f"(v.w) : "memory");
}
__device__ __forceinline__ float f2tf(float f) {
    unsigned r;
    asm("cvt.rna.tf32.f32 %0, %1;" : "=r"(r) : "f"(f));
    return __uint_as_float(r);
}
__device__ __forceinline__ void mma_tf32(float d[4],
                                         unsigned a0, unsigned a1, unsigned a2, unsigned a3,
                                         unsigned b0, unsigned b1) {
    asm volatile("mma.sync.aligned.m16n8k8.row.col.f32.tf32.tf32.f32 "
                 "{%0,%1,%2,%3}, {%4,%5,%6,%7}, {%8,%9}, {%0,%1,%2,%3};\n"
                 : "+f"(d[0]), "+f"(d[1]), "+f"(d[2]), "+f"(d[3])
                 : "r"(a0), "r"(a1), "r"(a2), "r"(a3), "r"(b0), "r"(b1));
}

// ---------------- zero ----------------
__global__ void k_zero(float* __restrict__ p, int n) {
    int i = blockIdx.x * blockDim.x + threadIdx.x;
    int stride = gridDim.x * blockDim.x;
    for (; i < n; i += stride) p[i] = 0.0f;
}

// ---------------- conv1 (C=3): per-edge full evaluation ----------------
__global__ void k_conv1(const float* __restrict__ x, const int* __restrict__ ei,
                        const float* __restrict__ ea,
                        const float* __restrict__ Wf, const float* __restrict__ bf,
                        const float* __restrict__ Ws, const float* __restrict__ bs,
                        float* __restrict__ agg) {
    __shared__ float sWf[38 * 3], sWs[38 * 3], sbf[3], sbs[3];
    int t = threadIdx.x;
    if (t < 114) { sWf[t] = Wf[t]; sWs[t] = Ws[t]; }
    if (t < 3)   { sbf[t] = bf[t]; sbs[t] = bs[t]; }
    __syncthreads();
    int e = blockIdx.x * blockDim.x + t;
    if (e >= N_EDGES) return;
    int src = ei[e];
    int dst = ei[N_EDGES + e];
    float z[38];
    z[0] = x[dst * 3 + 0]; z[1] = x[dst * 3 + 1]; z[2] = x[dst * 3 + 2];
    z[3] = x[src * 3 + 0]; z[4] = x[src * 3 + 1]; z[5] = x[src * 3 + 2];
#pragma unroll
    for (int k = 0; k < 32; k++) z[6 + k] = ea[e * 32 + k];
#pragma unroll
    for (int c = 0; c < 3; c++) {
        float lf = sbf[c], ls = sbs[c];
#pragma unroll
        for (int k = 0; k < 38; k++) {
            lf += z[k] * sWf[k * 3 + c];
            ls += z[k] * sWs[k * 3 + c];
        }
        float m = sigmoidf_(lf) * softplusf_(ls);
        atomicAdd(&agg[dst * 3 + c], m);
    }
}

// ---------------- node projection after conv1 ----------------
__global__ void k_node1(const float* __restrict__ x, const float* __restrict__ agg,
                        const float* __restrict__ Wp, const float* __restrict__ bp,
                        float* __restrict__ h) {
    int n = blockIdx.x;
    int c = threadIdx.x;
    __shared__ float sx[3];
    if (c < 3) sx[c] = x[n * 3 + c] + agg[n * 3 + c];
    __syncthreads();
    float v = bp[c] + sx[0] * Wp[c] + sx[1] * Wp[128 + c] + sx[2] * Wp[256 + c];
    h[n * HID + c] = fmaxf(v, 0.0f);
}

// ---------------- per-node projections via tf32 mma ----------------
// part 0: PA[:,0:128]   = h @ Wf[0:128,:]   + bf
// part 1: PA[:,128:256] = h @ Ws[0:128,:]   + bs
// part 2: PB[:,0:128]   = h @ Wf[128:256,:]
// part 3: PB[:,128:256] = h @ Ws[128:256,:]
__global__ __launch_bounds__(256) void k_proj_mma(
        const float* __restrict__ h,
        const float* __restrict__ Wf, const float* __restrict__ Ws,
        const float* __restrict__ bf, const float* __restrict__ bs,
        __half* __restrict__ PA, __half* __restrict__ PB) {
    __shared__ float hs[128][33];
    __shared__ float ws[32][132];

    int part = blockIdx.y;
    const float* W; const float* bias; __half* out; int coloff;
    if (part == 0)      { W = Wf;             bias = bf;      out = PA; coloff = 0;   }
    else if (part == 1) { W = Ws;             bias = bs;      out = PA; coloff = 128; }
    else if (part == 2) { W = Wf + 128 * 128; bias = nullptr; out = PB; coloff = 0;   }
    else                { W = Ws + 128 * 128; bias = nullptr; out = PB; coloff = 128; }

    int t = threadIdx.x;
    int lane = t & 31;
    int w = t >> 5;
    int g = lane >> 2;
    int tig = lane & 3;
    int n0 = blockIdx.x * 128;

    float acc[16][4];
#pragma unroll
    for (int i = 0; i < 16; i++)
#pragma unroll
        for (int j = 0; j < 4; j++) acc[i][j] = 0.0f;

    for (int kc = 0; kc < 4; kc++) {
        int k0 = kc * 32;
        // stage h tile (128 x 32) as tf32
#pragma unroll
        for (int j = 0; j < 4; j++) {
            int idx4 = t + j * 256;
            int row = idx4 >> 3;
            int c = (idx4 & 7) * 4;
            float4 v = make_float4(0.f, 0.f, 0.f, 0.f);
            int n = n0 + row;
            if (n < N_NODES) v = *(const float4*)&h[n * 128 + k0 + c];
            hs[row][c + 0] = f2tf(v.x); hs[row][c + 1] = f2tf(v.y);
            hs[row][c + 2] = f2tf(v.z); hs[row][c + 3] = f2tf(v.w);
        }
        // stage W tile (32 x 128) as tf32
#pragma unroll
        for (int j = 0; j < 4; j++) {
            int idx4 = t + j * 256;
            int row = idx4 >> 5;
            int c = (idx4 & 31) * 4;
            float4 v = *(const float4*)&W[(k0 + row) * 128 + c];
            ws[row][c + 0] = f2tf(v.x); ws[row][c + 1] = f2tf(v.y);
            ws[row][c + 2] = f2tf(v.z); ws[row][c + 3] = f2tf(v.w);
        }
        __syncthreads();
        int r0 = w * 16;
#pragma unroll
        for (int ks = 0; ks < 4; ks++) {
            int kk = ks * 8;
            unsigned a0 = __float_as_uint(hs[r0 + g][kk + tig]);
            unsigned a1 = __float_as_uint(hs[r0 + g + 8][kk + tig]);
            unsigned a2 = __float_as_uint(hs[r0 + g][kk + tig + 4]);
            unsigned a3 = __float_as_uint(hs[r0 + g + 8][kk + tig + 4]);
#pragma unroll
            for (int nt = 0; nt < 16; nt++) {
                unsigned b0 = __float_as_uint(ws[kk + tig][nt * 8 + g]);
                unsigned b1 = __float_as_uint(ws[kk + tig + 4][nt * 8 + g]);
                mma_tf32(acc[nt], a0, a1, a2, a3, b0, b1);
            }
        }
        __syncthreads();
    }
    // epilogue
    int r0 = n0 + w * 16;
#pragma unroll
    for (int nt = 0; nt < 16; nt++) {
        int c = nt * 8 + 2 * tig;
        float b0 = 0.f, b1 = 0.f;
        if (bias) { b0 = bias[c]; b1 = bias[c + 1]; }
        int n = r0 + g;
        if (n < N_NODES)
            *(half2*)&out[n * 256 + coloff + c] = __floats2half2_rn(acc[nt][0] + b0, acc[nt][1] + b1);
        n = r0 + g + 8;
        if (n < N_NODES)
            *(half2*)&out[n * 256 + coloff + c] = __floats2half2_rn(acc[nt][2] + b0, acc[nt][3] + b1);
    }
}

// ---------------- fused edge kernel ----------------
// Phase 1: E[64x256] = ea_tile[64x32] @ [Wef|Wes] via tf32 mma (E stays in smem)
// Phase 2: lf = PAf[dst]+PBf[src]+Ef; ls = ...; m = sigmoid(lf)*softplus(ls); red agg[dst]
#define WS_STRIDE 264
#define EA_STRIDE 33
#define EH_STRIDE 264
__global__ __launch_bounds__(256) void k_edge_fused(
        const int* __restrict__ ei, const float* __restrict__ ea,
        const __half* __restrict__ PA, const __half* __restrict__ PB,
        const float* __restrict__ Wf, const float* __restrict__ Ws,
        float* __restrict__ agg) {
    extern __shared__ float smem[];
    float* ws  = smem;                          // [32][264] tf32 W (f|s)
    float* eas = ws + 32 * WS_STRIDE;           // [64][33] tf32 ea tile
    __half* Eh = (__half*)(eas + 64 * EA_STRIDE); // [64][264] E tile fp16

    int t = threadIdx.x;
    int lane = t & 31;
    int w = t >> 5;
    int g = lane >> 2;
    int tig = lane & 3;

    // load W (rows 256..287 of Wf/Ws), convert to tf32, once per block
#pragma unroll
    for (int j = 0; j < 8; j++) {
        int idx4 = t + j * 256;
        int row = idx4 >> 6;
        int c = (idx4 & 63) * 4;
        const float* src = (c < 128) ? &Wf[(256 + row) * 128 + c]
                                     : &Ws[(256 + row) * 128 + (c - 128)];
        float4 v = *(const float4*)src;
        float* d = &ws[row * WS_STRIDE + c];
        d[0] = f2tf(v.x); d[1] = f2tf(v.y); d[2] = f2tf(v.z); d[3] = f2tf(v.w);
    }
    __syncthreads();

    int erow0 = (w & 3) * 16;
    int col0 = (w >> 2) * 128;

    for (int tile = blockIdx.x; tile < NTILES; tile += gridDim.x) {
        long e0 = (long)tile * ETILE;
        // stage ea tile (64 x 32) as tf32
        {
            const float4* src = (const float4*)&ea[e0 * 32];
            float4 v0 = src[t * 2];
            float4 v1 = src[t * 2 + 1];
            int row = t >> 2;
            int c = (t & 3) * 8;
            float* d = &eas[row * EA_STRIDE + c];
            d[0] = f2tf(v0.x); d[1] = f2tf(v0.y); d[2] = f2tf(v0.z); d[3] = f2tf(v0.w);
            d[4] = f2tf(v1.x); d[5] = f2tf(v1.y); d[6] = f2tf(v1.z); d[7] = f2tf(v1.w);
        }
        __syncthreads();

        // phase 1: mma  (warp tile: 16 edges x 128 cols)
        {
            float acc[16][4];
#pragma unroll
            for (int i = 0; i < 16; i++)
#pragma unroll
                for (int j = 0; j < 4; j++) acc[i][j] = 0.0f;
#pragma unroll
            for (int ks = 0; ks < 4; ks++) {
                int kk = ks * 8;
                unsigned a0 = __float_as_uint(eas[(erow0 + g) * EA_STRIDE + kk + tig]);
                unsigned a1 = __float_as_uint(eas[(erow0 + g + 8) * EA_STRIDE + kk + tig]);
                unsigned a2 = __float_as_uint(eas[(erow0 + g) * EA_STRIDE + kk + tig + 4]);
                unsigned a3 = __float_as_uint(eas[(erow0 + g + 8) * EA_STRIDE + kk + tig + 4]);
#pragma unroll
                for (int nt = 0; nt < 16; nt++) {
                    unsigned b0 = __float_as_uint(ws[(kk + tig) * WS_STRIDE + col0 + nt * 8 + g]);
                    unsigned b1 = __float_as_uint(ws[(kk + tig + 4) * WS_STRIDE + col0 + nt * 8 + g]);
                    mma_tf32(acc[nt], a0, a1, a2, a3, b0, b1);
                }
            }
            // store E tile to smem (fp16)
#pragma unroll
            for (int nt = 0; nt < 16; nt++) {
                int c = col0 + nt * 8 + 2 * tig;
                *(half2*)&Eh[(erow0 + g) * EH_STRIDE + c]     = __floats2half2_rn(acc[nt][0], acc[nt][1]);
                *(half2*)&Eh[(erow0 + g + 8) * EH_STRIDE + c] = __floats2half2_rn(acc[nt][2], acc[nt][3]);
            }
        }
        __syncthreads();

        // phase 2: gather + gate + scatter (warp w handles edges w*8 .. w*8+7)
#pragma unroll
        for (int j = 0; j < 8; j++) {
            int le = w * 8 + j;
            int e = (int)e0 + le;
            int src = ei[e];
            int dst = ei[N_EDGES + e];

            uint2 efu = *(const uint2*)&Eh[le * EH_STRIDE + lane * 4];
            uint2 esu = *(const uint2*)&Eh[le * EH_STRIDE + 128 + lane * 4];
            uint2 pafu = *(const uint2*)&PA[(size_t)dst * 256 + lane * 4];
            uint2 pasu = *(const uint2*)&PA[(size_t)dst * 256 + 128 + lane * 4];
            uint2 pbfu = *(const uint2*)&PB[(size_t)src * 256 + lane * 4];
            uint2 pbsu = *(const uint2*)&PB[(size_t)src * 256 + 128 + lane * 4];

            float2 ef0 = __half22float2(*(half2*)&efu.x),  ef1 = __half22float2(*(half2*)&efu.y);
            float2 es0 = __half22float2(*(half2*)&esu.x),  es1 = __half22float2(*(half2*)&esu.y);
            float2 af0 = __half22float2(*(half2*)&pafu.x), af1 = __half22float2(*(half2*)&pafu.y);
            float2 as0 = __half22float2(*(half2*)&pasu.x), as1 = __half22float2(*(half2*)&pasu.y);
            float2 bf0 = __half22float2(*(half2*)&pbfu.x), bf1 = __half22float2(*(half2*)&pbfu.y);
            float2 bs0 = __half22float2(*(half2*)&pbsu.x), bs1 = __half22float2(*(half2*)&pbsu.y);

            float lf0 = ef0.x + af0.x + bf0.x, lf1 = ef0.y + af0.y + bf0.y;
            float lf2 = ef1.x + af1.x + bf1.x, lf3 = ef1.y + af1.y + bf1.y;
            float ls0 = es0.x + as0.x + bs0.x, ls1 = es0.y + as0.y + bs0.y;
            float ls2 = es1.x + as1.x + bs1.x, ls3 = es1.y + as1.y + bs1.y;

            float4 m;
            m.x = sigmoidf_(lf0) * softplusf_(ls0);
            m.y = sigmoidf_(lf1) * softplusf_(ls1);
            m.z = sigmoidf_(lf2) * softplusf_(ls2);
            m.w = sigmoidf_(lf3) * softplusf_(ls3);
            red4(&agg[(size_t)dst * HID + lane * 4], m);
        }
        __syncthreads();
    }
}

// ---------------- residual + relu ----------------
__global__ void k_update(float* __restrict__ h, const float* __restrict__ agg, int n) {
    int i = blockIdx.x * blockDim.x + threadIdx.x;
    int stride = gridDim.x * blockDim.x;
    for (; i < n; i += stride) h[i] = fmaxf(h[i] + agg[i], 0.0f);
}

// ---------------- pooling (batch sorted) ----------------
__global__ void k_pool(const float* __restrict__ h, const int* __restrict__ batch,
                       float* __restrict__ pool, float* __restrict__ cnt) {
    const int NPB = 256;
    int n0 = blockIdx.x * NPB;
    if (n0 >= N_NODES) return;
    int c = threadIdx.x;
    float s = 0.0f;
    int cur = batch[n0];
    int mycnt = 0;
    for (int i = 0; i < NPB; i++) {
        int n = n0 + i;
        if (n >= N_NODES) break;
        int b = batch[n];
        if (b != cur) {
            atomicAdd(&pool[cur * HID + c], s);
            if (c == 0) atomicAdd(&cnt[cur], (float)mycnt);
            s = 0.0f; mycnt = 0; cur = b;
        }
        s += h[n * HID + c];
        mycnt++;
    }
    atomicAdd(&pool[cur * HID + c], s);
    if (c == 0) atomicAdd(&cnt[cur], (float)mycnt);
}

// ---------------- head ----------------
__global__ void k_head(const float* __restrict__ pool, const float* __restrict__ cnt,
                       const float* __restrict__ W1, const float* __restrict__ b1,
                       const float* __restrict__ W2, const float* __restrict__ b2,
                       float* __restrict__ out) {
    int g = blockIdx.x;
    int c = threadIdx.x;
    __shared__ float p[128];
    __shared__ float t1[128];
    float invc = 1.0f / fmaxf(cnt[g], 1.0f);
    p[c] = pool[g * HID + c] * invc;
    __syncthreads();
    float v = b1[c];
#pragma unroll 16
    for (int k = 0; k < 128; k++) v += p[k] * W1[k * 128 + c];
    t1[c] = fmaxf(v, 0.0f);
    __syncthreads();
    if (c < 3) {
        float o = b2[c];
        for (int k = 0; k < 128; k++) o += t1[k] * W2[k * 3 + c];
        out[g * 3 + c] = o;
    }
}

// ---------------- launch ----------------
extern "C" void kernel_launch(void* const* d_in, const int* in_sizes, int n_in,
                              void* d_out, int out_size) {
    const float* x   = (const float*)d_in[0];
    const int*   ei  = (const int*)d_in[1];
    const float* ea  = (const float*)d_in[2];
    const int*   bat = (const int*)d_in[3];
    const float* Wf1 = (const float*)d_in[4];
    const float* bf1 = (const float*)d_in[5];
    const float* Ws1 = (const float*)d_in[6];
    const float* bs1 = (const float*)d_in[7];
    const float* Wp  = (const float*)d_in[8];
    const float* bp  = (const float*)d_in[9];
    const float* Wc[2]  = { (const float*)d_in[10], (const float*)d_in[14] };
    const float* bcf[2] = { (const float*)d_in[11], (const float*)d_in[15] };
    const float* Wsc[2] = { (const float*)d_in[12], (const float*)d_in[16] };
    const float* bcs[2] = { (const float*)d_in[13], (const float*)d_in[17] };
    const float* W1  = (const float*)d_in[18];
    const float* b1  = (const float*)d_in[19];
    const float* W2  = (const float*)d_in[20];
    const float* b2  = (const float*)d_in[21];
    float* out = (float*)d_out;

    float *pH, *pAgg, *pPool;
    __half *pPA, *pPB;
    cudaGetSymbolAddress((void**)&pH,    g_h);
    cudaGetSymbolAddress((void**)&pPA,   g_PA);
    cudaGetSymbolAddress((void**)&pPB,   g_PB);
    cudaGetSymbolAddress((void**)&pAgg,  g_agg);
    cudaGetSymbolAddress((void**)&pPool, g_pool);

    const int EDGE_SMEM = (32 * WS_STRIDE + 64 * EA_STRIDE) * 4 + 64 * EH_STRIDE * 2;
    cudaFuncSetAttribute(k_edge_fused, cudaFuncAttributeMaxDynamicSharedMemorySize, EDGE_SMEM);

    // conv1
    k_zero<<<512, 256>>>(pAgg, N_NODES * 3);
    k_conv1<<<(N_EDGES + 255) / 256, 256>>>(x, ei, ea, Wf1, bf1, Ws1, bs1, pAgg);
    k_node1<<<N_NODES, 128>>>(x, pAgg, Wp, bp, pH);

    // hidden convs
    for (int l = 0; l < 2; l++) {
        dim3 pg((N_NODES + 127) / 128, 4);
        k_proj_mma<<<pg, 256>>>(pH, Wc[l], Wsc[l], bcf[l], bcs[l], pPA, pPB);
        k_zero<<<2048, 256>>>(pAgg, N_NODES * HID);
        k_edge_fused<<<296, 256, EDGE_SMEM>>>(ei, ea, pPA, pPB, Wc[l], Wsc[l], pAgg);
        k_update<<<2048, 256>>>(pH, pAgg, N_NODES * HID);
    }

    // pooling + head
    k_zero<<<64, 256>>>(pPool, NGRAPH * HID + NGRAPH);
    k_pool<<<(N_NODES + 255) / 256, 128>>>(pH, bat, pPool, pPool + NGRAPH * HID);
    k_head<<<NGRAPH, 128>>>(pPool, pPool + NGRAPH * HID, W1, b1, W2, b2, out);
}

// round 3
// speedup vs baseline: 1.4994x; 1.2431x over previous
#include <cuda_runtime.h>
#include <cuda_fp16.h>
#include <math.h>

#define N_NODES 100000
#define N_EDGES 1600000
#define HID 128
#define NGRAPH 64
#define ETILE 64
#define NTILES (N_EDGES / ETILE)

// ---------------- device scratch ----------------
__device__ float  g_h[N_NODES * HID];
__device__ __half g_PA[N_NODES * 256];   // per-node dst-parts: [f(128)|s(128)] (+bias)
__device__ __half g_PB[N_NODES * 256];   // per-node src-parts
__device__ float  g_agg[N_NODES * HID];
__device__ float  g_pool[NGRAPH * HID + NGRAPH];

// ---------------- helpers ----------------
__device__ __forceinline__ float sigmoidf_(float x) { return 1.0f / (1.0f + __expf(-x)); }
__device__ __forceinline__ float softplusf_(float x) {
    return fmaxf(x, 0.0f) + __logf(1.0f + __expf(-fabsf(x)));
}
__device__ __forceinline__ void red4(float* p, float4 v) {
    asm volatile("red.global.add.v4.f32 [%0], {%1,%2,%3,%4};"
                 :: "l"(p), "f"(v.x), "f"(v.y), "f"(v.z), "f"(v.w) : "memory");
}
__device__ __forceinline__ float f2tf(float f) {
    unsigned r;
    asm("cvt.rna.tf32.f32 %0, %1;" : "=r"(r) : "f"(f));
    return __uint_as_float(r);
}
__device__ __forceinline__ void mma_tf32(float d[4],
                                         unsigned a0, unsigned a1, unsigned a2, unsigned a3,
                                         unsigned b0, unsigned b1) {
    asm volatile("mma.sync.aligned.m16n8k8.row.col.f32.tf32.tf32.f32 "
                 "{%0,%1,%2,%3}, {%4,%5,%6,%7}, {%8,%9}, {%0,%1,%2,%3};\n"
                 : "+f"(d[0]), "+f"(d[1]), "+f"(d[2]), "+f"(d[3])
                 : "r"(a0), "r"(a1), "r"(a2), "r"(a3), "r"(b0), "r"(b1));
}
__device__ __forceinline__ void mma_f16(float d[4],
                                        unsigned a0, unsigned a1, unsigned a2, unsigned a3,
                                        unsigned b0, unsigned b1) {
    asm volatile("mma.sync.aligned.m16n8k16.row.col.f32.f16.f16.f32 "
                 "{%0,%1,%2,%3}, {%4,%5,%6,%7}, {%8,%9}, {%0,%1,%2,%3};\n"
                 : "+f"(d[0]), "+f"(d[1]), "+f"(d[2]), "+f"(d[3])
                 : "r"(a0), "r"(a1), "r"(a2), "r"(a3), "r"(b0), "r"(b1));
}

// ---------------- zero ----------------
__global__ void k_zero(float* __restrict__ p, int n) {
    int i = blockIdx.x * blockDim.x + threadIdx.x;
    int stride = gridDim.x * blockDim.x;
    for (; i < n; i += stride) p[i] = 0.0f;
}

// ---------------- conv1 (C=3) ----------------
__global__ void k_conv1(const float* __restrict__ x, const int* __restrict__ ei,
                        const float* __restrict__ ea,
                        const float* __restrict__ Wf, const float* __restrict__ bf,
                        const float* __restrict__ Ws, const float* __restrict__ bs,
                        float* __restrict__ agg) {
    __shared__ float sWf[38 * 3], sWs[38 * 3], sbf[3], sbs[3];
    int t = threadIdx.x;
    if (t < 114) { sWf[t] = Wf[t]; sWs[t] = Ws[t]; }
    if (t < 3)   { sbf[t] = bf[t]; sbs[t] = bs[t]; }
    __syncthreads();
    int e = blockIdx.x * blockDim.x + t;
    if (e >= N_EDGES) return;
    int src = ei[e];
    int dst = ei[N_EDGES + e];
    float z[38];
    z[0] = x[dst * 3 + 0]; z[1] = x[dst * 3 + 1]; z[2] = x[dst * 3 + 2];
    z[3] = x[src * 3 + 0]; z[4] = x[src * 3 + 1]; z[5] = x[src * 3 + 2];
#pragma unroll
    for (int k = 0; k < 32; k++) z[6 + k] = ea[e * 32 + k];
#pragma unroll
    for (int c = 0; c < 3; c++) {
        float lf = sbf[c], ls = sbs[c];
#pragma unroll
        for (int k = 0; k < 38; k++) {
            lf += z[k] * sWf[k * 3 + c];
            ls += z[k] * sWs[k * 3 + c];
        }
        float m = sigmoidf_(lf) * softplusf_(ls);
        atomicAdd(&agg[dst * 3 + c], m);
    }
}

// ---------------- node projection after conv1 ----------------
__global__ void k_node1(const float* __restrict__ x, const float* __restrict__ agg,
                        const float* __restrict__ Wp, const float* __restrict__ bp,
                        float* __restrict__ h) {
    int n = blockIdx.x;
    int c = threadIdx.x;
    __shared__ float sx[3];
    if (c < 3) sx[c] = x[n * 3 + c] + agg[n * 3 + c];
    __syncthreads();
    float v = bp[c] + sx[0] * Wp[c] + sx[1] * Wp[128 + c] + sx[2] * Wp[256 + c];
    h[n * HID + c] = fmaxf(v, 0.0f);
}

// ---------------- per-node projections via tf32 mma ----------------
__global__ __launch_bounds__(256) void k_proj_mma(
        const float* __restrict__ h,
        const float* __restrict__ Wf, const float* __restrict__ Ws,
        const float* __restrict__ bf, const float* __restrict__ bs,
        __half* __restrict__ PA, __half* __restrict__ PB) {
    __shared__ float hs[128][33];
    __shared__ float ws[32][132];

    int part = blockIdx.y;
    const float* W; const float* bias; __half* out; int coloff;
    if (part == 0)      { W = Wf;             bias = bf;      out = PA; coloff = 0;   }
    else if (part == 1) { W = Ws;             bias = bs;      out = PA; coloff = 128; }
    else if (part == 2) { W = Wf + 128 * 128; bias = nullptr; out = PB; coloff = 0;   }
    else                { W = Ws + 128 * 128; bias = nullptr; out = PB; coloff = 128; }

    int t = threadIdx.x;
    int lane = t & 31;
    int w = t >> 5;
    int g = lane >> 2;
    int tig = lane & 3;
    int n0 = blockIdx.x * 128;

    float acc[16][4];
#pragma unroll
    for (int i = 0; i < 16; i++)
#pragma unroll
        for (int j = 0; j < 4; j++) acc[i][j] = 0.0f;

    for (int kc = 0; kc < 4; kc++) {
        int k0 = kc * 32;
#pragma unroll
        for (int j = 0; j < 4; j++) {
            int idx4 = t + j * 256;
            int row = idx4 >> 3;
            int c = (idx4 & 7) * 4;
            float4 v = make_float4(0.f, 0.f, 0.f, 0.f);
            int n = n0 + row;
            if (n < N_NODES) v = *(const float4*)&h[n * 128 + k0 + c];
            hs[row][c + 0] = f2tf(v.x); hs[row][c + 1] = f2tf(v.y);
            hs[row][c + 2] = f2tf(v.z); hs[row][c + 3] = f2tf(v.w);
        }
#pragma unroll
        for (int j = 0; j < 4; j++) {
            int idx4 = t + j * 256;
            int row = idx4 >> 5;
            int c = (idx4 & 31) * 4;
            float4 v = *(const float4*)&W[(k0 + row) * 128 + c];
            ws[row][c + 0] = f2tf(v.x); ws[row][c + 1] = f2tf(v.y);
            ws[row][c + 2] = f2tf(v.z); ws[row][c + 3] = f2tf(v.w);
        }
        __syncthreads();
        int r0 = w * 16;
#pragma unroll
        for (int ks = 0; ks < 4; ks++) {
            int kk = ks * 8;
            unsigned a0 = __float_as_uint(hs[r0 + g][kk + tig]);
            unsigned a1 = __float_as_uint(hs[r0 + g + 8][kk + tig]);
            unsigned a2 = __float_as_uint(hs[r0 + g][kk + tig + 4]);
            unsigned a3 = __float_as_uint(hs[r0 + g + 8][kk + tig + 4]);
#pragma unroll
            for (int nt = 0; nt < 16; nt++) {
                unsigned b0 = __float_as_uint(ws[kk + tig][nt * 8 + g]);
                unsigned b1 = __float_as_uint(ws[kk + tig + 4][nt * 8 + g]);
                mma_tf32(acc[nt], a0, a1, a2, a3, b0, b1);
            }
        }
        __syncthreads();
    }
    int r0 = n0 + w * 16;
#pragma unroll
    for (int nt = 0; nt < 16; nt++) {
        int c = nt * 8 + 2 * tig;
        float b0 = 0.f, b1 = 0.f;
        if (bias) { b0 = bias[c]; b1 = bias[c + 1]; }
        int n = r0 + g;
        if (n < N_NODES)
            *(half2*)&out[n * 256 + coloff + c] = __floats2half2_rn(acc[nt][0] + b0, acc[nt][1] + b1);
        n = r0 + g + 8;
        if (n < N_NODES)
            *(half2*)&out[n * 256 + coloff + c] = __floats2half2_rn(acc[nt][2] + b0, acc[nt][3] + b1);
    }
}

// ---------------- fused edge kernel (fp16 mma, 3 blocks/SM) ----------------
#define WT_S 40
#define EA_S 40
#define EH_S 264
__global__ __launch_bounds__(256, 3) void k_edge_fused(
        const int* __restrict__ ei, const float* __restrict__ ea,
        const __half* __restrict__ PA, const __half* __restrict__ PB,
        const float* __restrict__ Wf, const float* __restrict__ Ws,
        float* __restrict__ agg) {
    extern __shared__ __half sm[];
    __half* wsT  = sm;                          // 256*40  W transposed [col][k]
    __half* seas = sm + 256 * WT_S;             // 64*40   ea tile
    __half* Eh   = sm + 256 * WT_S + 64 * EA_S; // 64*264  E tile

    int t = threadIdx.x;
    int lane = t & 31;
    int w = t >> 5;
    int g = lane >> 2;
    int tig = lane & 3;

    // stage W transposed: wsT[c][k] = W[256+k][c], fp16
#pragma unroll
    for (int j = 0; j < 32; j++) {
        int idx = t + j * 256;             // 8192 elements
        int k = idx >> 8;
        int c = idx & 255;
        float v = (c < 128) ? Wf[(256 + k) * 128 + c]
                            : Ws[(256 + k) * 128 + (c - 128)];
        wsT[c * WT_S + k] = __float2half_rn(v);
    }
    __syncthreads();

    int erow0 = (w & 3) * 16;
    int col0 = (w >> 2) * 128;

    for (int tile = blockIdx.x; tile < NTILES; tile += gridDim.x) {
        long e0 = (long)tile * ETILE;
        // stage ea tile (64 x 32) fp16
        {
            const float4* src = (const float4*)&ea[e0 * 32];
            float4 v0 = src[t * 2];
            float4 v1 = src[t * 2 + 1];
            int row = t >> 2;
            int c = (t & 3) * 8;
            __half* d = &seas[row * EA_S + c];
            *(half2*)&d[0] = __floats2half2_rn(v0.x, v0.y);
            *(half2*)&d[2] = __floats2half2_rn(v0.z, v0.w);
            *(half2*)&d[4] = __floats2half2_rn(v1.x, v1.y);
            *(half2*)&d[6] = __floats2half2_rn(v1.z, v1.w);
        }
        __syncthreads();

        // phase 1: E = ea @ [Wef|Wes] via fp16 mma; warp tile 16x128 in 2 halves
#pragma unroll
        for (int h2i = 0; h2i < 2; h2i++) {
            float acc[8][4];
#pragma unroll
            for (int i = 0; i < 8; i++)
#pragma unroll
                for (int j = 0; j < 4; j++) acc[i][j] = 0.0f;
#pragma unroll
            for (int ks = 0; ks < 2; ks++) {
                int kb = ks * 16;
                unsigned a0 = *(const unsigned*)&seas[(erow0 + g) * EA_S + kb + 2 * tig];
                unsigned a1 = *(const unsigned*)&seas[(erow0 + g + 8) * EA_S + kb + 2 * tig];
                unsigned a2 = *(const unsigned*)&seas[(erow0 + g) * EA_S + kb + 2 * tig + 8];
                unsigned a3 = *(const unsigned*)&seas[(erow0 + g + 8) * EA_S + kb + 2 * tig + 8];
#pragma unroll
                for (int nt = 0; nt < 8; nt++) {
                    int col = col0 + h2i * 64 + nt * 8 + g;
                    unsigned b0 = *(const unsigned*)&wsT[col * WT_S + kb + 2 * tig];
                    unsigned b1 = *(const unsigned*)&wsT[col * WT_S + kb + 2 * tig + 8];
                    mma_f16(acc[nt], a0, a1, a2, a3, b0, b1);
                }
            }
#pragma unroll
            for (int nt = 0; nt < 8; nt++) {
                int c = col0 + h2i * 64 + nt * 8 + 2 * tig;
                *(half2*)&Eh[(erow0 + g) * EH_S + c]     = __floats2half2_rn(acc[nt][0], acc[nt][1]);
                *(half2*)&Eh[(erow0 + g + 8) * EH_S + c] = __floats2half2_rn(acc[nt][2], acc[nt][3]);
            }
        }
        __syncthreads();

        // phase 2: gather + gate + scatter (warp w: edges w*8 .. w*8+7)
        int srcs[8], dsts[8];
#pragma unroll
        for (int j = 0; j < 8; j++) {
            int e = (int)e0 + w * 8 + j;
            srcs[j] = ei[e];
            dsts[j] = ei[N_EDGES + e];
        }
#pragma unroll
        for (int j = 0; j < 8; j++) {
            int le = w * 8 + j;
            int src = srcs[j];
            int dst = dsts[j];

            uint2 efu = *(const uint2*)&Eh[le * EH_S + lane * 4];
            uint2 esu = *(const uint2*)&Eh[le * EH_S + 128 + lane * 4];
            uint2 pafu = *(const uint2*)&PA[(size_t)dst * 256 + lane * 4];
            uint2 pasu = *(const uint2*)&PA[(size_t)dst * 256 + 128 + lane * 4];
            uint2 pbfu = *(const uint2*)&PB[(size_t)src * 256 + lane * 4];
            uint2 pbsu = *(const uint2*)&PB[(size_t)src * 256 + 128 + lane * 4];

            float2 ef0 = __half22float2(*(half2*)&efu.x),  ef1 = __half22float2(*(half2*)&efu.y);
            float2 es0 = __half22float2(*(half2*)&esu.x),  es1 = __half22float2(*(half2*)&esu.y);
            float2 af0 = __half22float2(*(half2*)&pafu.x), af1 = __half22float2(*(half2*)&pafu.y);
            float2 as0 = __half22float2(*(half2*)&pasu.x), as1 = __half22float2(*(half2*)&pasu.y);
            float2 bf0 = __half22float2(*(half2*)&pbfu.x), bf1 = __half22float2(*(half2*)&pbfu.y);
            float2 bs0 = __half22float2(*(half2*)&pbsu.x), bs1 = __half22float2(*(half2*)&pbsu.y);

            float4 m;
            m.x = sigmoidf_(ef0.x + af0.x + bf0.x) * softplusf_(es0.x + as0.x + bs0.x);
            m.y = sigmoidf_(ef0.y + af0.y + bf0.y) * softplusf_(es0.y + as0.y + bs0.y);
            m.z = sigmoidf_(ef1.x + af1.x + bf1.x) * softplusf_(es1.x + as1.x + bs1.x);
            m.w = sigmoidf_(ef1.y + af1.y + bf1.y) * softplusf_(es1.y + as1.y + bs1.y);
            red4(&agg[(size_t)dst * HID + lane * 4], m);
        }
        __syncthreads();
    }
}

// ---------------- residual + relu ----------------
__global__ void k_update(float* __restrict__ h, const float* __restrict__ agg, int n) {
    int i = blockIdx.x * blockDim.x + threadIdx.x;
    int stride = gridDim.x * blockDim.x;
    for (; i < n; i += stride) h[i] = fmaxf(h[i] + agg[i], 0.0f);
}

// ---------------- pooling (batch sorted) ----------------
__global__ void k_pool(const float* __restrict__ h, const int* __restrict__ batch,
                       float* __restrict__ pool, float* __restrict__ cnt) {
    const int NPB = 256;
    int n0 = blockIdx.x * NPB;
    if (n0 >= N_NODES) return;
    int c = threadIdx.x;
    float s = 0.0f;
    int cur = batch[n0];
    int mycnt = 0;
    for (int i = 0; i < NPB; i++) {
        int n = n0 + i;
        if (n >= N_NODES) break;
        int b = batch[n];
        if (b != cur) {
            atomicAdd(&pool[cur * HID + c], s);
            if (c == 0) atomicAdd(&cnt[cur], (float)mycnt);
            s = 0.0f; mycnt = 0; cur = b;
        }
        s += h[n * HID + c];
        mycnt++;
    }
    atomicAdd(&pool[cur * HID + c], s);
    if (c == 0) atomicAdd(&cnt[cur], (float)mycnt);
}

// ---------------- head ----------------
__global__ void k_head(const float* __restrict__ pool, const float* __restrict__ cnt,
                       const float* __restrict__ W1, const float* __restrict__ b1,
                       const float* __restrict__ W2, const float* __restrict__ b2,
                       float* __restrict__ out) {
    int g = blockIdx.x;
    int c = threadIdx.x;
    __shared__ float p[128];
    __shared__ float t1[128];
    float invc = 1.0f / fmaxf(cnt[g], 1.0f);
    p[c] = pool[g * HID + c] * invc;
    __syncthreads();
    float v = b1[c];
#pragma unroll 16
    for (int k = 0; k < 128; k++) v += p[k] * W1[k * 128 + c];
    t1[c] = fmaxf(v, 0.0f);
    __syncthreads();
    if (c < 3) {
        float o = b2[c];
        for (int k = 0; k < 128; k++) o += t1[k] * W2[k * 3 + c];
        out[g * 3 + c] = o;
    }
}

// ---------------- launch ----------------
extern "C" void kernel_launch(void* const* d_in, const int* in_sizes, int n_in,
                              void* d_out, int out_size) {
    const float* x   = (const float*)d_in[0];
    const int*   ei  = (const int*)d_in[1];
    const float* ea  = (const float*)d_in[2];
    const int*   bat = (const int*)d_in[3];
    const float* Wf1 = (const float*)d_in[4];
    const float* bf1 = (const float*)d_in[5];
    const float* Ws1 = (const float*)d_in[6];
    const float* bs1 = (const float*)d_in[7];
    const float* Wp  = (const float*)d_in[8];
    const float* bp  = (const float*)d_in[9];
    const float* Wc[2]  = { (const float*)d_in[10], (const float*)d_in[14] };
    const float* bcf[2] = { (const float*)d_in[11], (const float*)d_in[15] };
    const float* Wsc[2] = { (const float*)d_in[12], (const float*)d_in[16] };
    const float* bcs[2] = { (const float*)d_in[13], (const float*)d_in[17] };
    const float* W1  = (const float*)d_in[18];
    const float* b1  = (const float*)d_in[19];
    const float* W2  = (const float*)d_in[20];
    const float* b2  = (const float*)d_in[21];
    float* out = (float*)d_out;

    float *pH, *pAgg, *pPool;
    __half *pPA, *pPB;
    cudaGetSymbolAddress((void**)&pH,    g_h);
    cudaGetSymbolAddress((void**)&pPA,   g_PA);
    cudaGetSymbolAddress((void**)&pPB,   g_PB);
    cudaGetSymbolAddress((void**)&pAgg,  g_agg);
    cudaGetSymbolAddress((void**)&pPool, g_pool);

    const int EDGE_SMEM = (256 * WT_S + 64 * EA_S + 64 * EH_S) * 2;
    cudaFuncSetAttribute(k_edge_fused, cudaFuncAttributeMaxDynamicSharedMemorySize, EDGE_SMEM);

    // conv1
    k_zero<<<512, 256>>>(pAgg, N_NODES * 3);
    k_conv1<<<(N_EDGES + 255) / 256, 256>>>(x, ei, ea, Wf1, bf1, Ws1, bs1, pAgg);
    k_node1<<<N_NODES, 128>>>(x, pAgg, Wp, bp, pH);

    // hidden convs
    for (int l = 0; l < 2; l++) {
        dim3 pg((N_NODES + 127) / 128, 4);
        k_proj_mma<<<pg, 256>>>(pH, Wc[l], Wsc[l], bcf[l], bcs[l], pPA, pPB);
        k_zero<<<2048, 256>>>(pAgg, N_NODES * HID);
        k_edge_fused<<<444, 256, EDGE_SMEM>>>(ei, ea, pPA, pPB, Wc[l], Wsc[l], pAgg);
        k_update<<<2048, 256>>>(pH, pAgg, N_NODES * HID);
    }

    // pooling + head
    k_zero<<<64, 256>>>(pPool, NGRAPH * HID + NGRAPH);
    k_pool<<<(N_NODES + 255) / 256, 128>>>(pH, bat, pPool, pPool + NGRAPH * HID);
    k_head<<<NGRAPH, 128>>>(pPool, pPool + NGRAPH * HID, W1, b1, W2, b2, out);
}